// round 6
// baseline (speedup 1.0000x reference)
#include <cuda_runtime.h>
#include <math.h>
#include <math_constants.h>

// Problem constants
#define BATCH   64
#define SEQ     256
#define NEMB    384
#define NHEAD   6
#define HD      64
#define BH      (BATCH*NHEAD)      // 384
#define MTOT    (BATCH*SEQ)        // 16384
#define N_QKV   (3*NEMB)           // 1152

#define PA  36          // A smem pitch (32 + 4)
#define PB  136         // B smem pitch (128 + 8)
#define NCHUNK (NEMB/32)            // 12

#define PKV 68          // attn K pitch
#define PVV 72          // attn V pitch

#define L2E 1.4426950408889634f

// Scratch
__device__ float g_q[BH*SEQ*HD];
__device__ float g_k[BH*SEQ*HD];
__device__ float g_v[BH*SEQ*HD];
__device__ float g_o[BH*SEQ*HD];
__device__ float g_xt[MTOT*NEMB];       // tf32-rounded x
__device__ float g_wat[NEMB*N_QKV];     // tf32-rounded w_attn
__device__ float g_wpt[NEMB*NEMB];      // tf32-rounded w_proj

__device__ __forceinline__ unsigned f2tf(float f) {
    unsigned u;
    asm("cvt.rna.tf32.f32 %0, %1;" : "=r"(u) : "f"(f));
    return u;
}

__device__ __forceinline__ void mma8(float* c, const unsigned* a, const unsigned* b) {
    asm volatile(
        "mma.sync.aligned.m16n8k8.row.col.f32.tf32.tf32.f32 "
        "{%0,%1,%2,%3}, {%4,%5,%6,%7}, {%8,%9}, {%0,%1,%2,%3};"
        : "+f"(c[0]), "+f"(c[1]), "+f"(c[2]), "+f"(c[3])
        : "r"(a[0]), "r"(a[1]), "r"(a[2]), "r"(a[3]),
          "r"(b[0]), "r"(b[1]));
}

__device__ __forceinline__ void cp16(unsigned* dst_smem, const void* src) {
    unsigned d = (unsigned)__cvta_generic_to_shared(dst_smem);
    asm volatile("cp.async.cg.shared.global [%0], [%1], 16;\n" :: "r"(d), "l"(src));
}
__device__ __forceinline__ void cp_commit() {
    asm volatile("cp.async.commit_group;\n");
}
template <int N> __device__ __forceinline__ void cp_wait() {
    asm volatile("cp.async.wait_group %0;\n" :: "n"(N));
}

// ---------------------------------------------------------------------------
// Kernel 0: tf32-round x, w_attn, w_proj into scratch (vectorized).
// ---------------------------------------------------------------------------
__global__ __launch_bounds__(256) void conv_tf32(
    const float* __restrict__ x, const float* __restrict__ wa,
    const float* __restrict__ wp)
{
    const int i = blockIdx.x*blockDim.x + threadIdx.x;
    const int NX4 = MTOT*NEMB/4, NA4 = NEMB*N_QKV/4, NP4 = NEMB*NEMB/4;
    if (i < NX4) {
        float4 v = ((const float4*)x)[i];
        ((uint4*)g_xt)[i] = make_uint4(f2tf(v.x),f2tf(v.y),f2tf(v.z),f2tf(v.w));
    }
    if (i < NA4) {
        float4 v = ((const float4*)wa)[i];
        ((uint4*)g_wat)[i] = make_uint4(f2tf(v.x),f2tf(v.y),f2tf(v.z),f2tf(v.w));
    }
    if (i < NP4) {
        float4 v = ((const float4*)wp)[i];
        ((uint4*)g_wpt)[i] = make_uint4(f2tf(v.x),f2tf(v.y),f2tf(v.z),f2tf(v.w));
    }
}

// GEMM smem: A 2 x 64 x PA, B 2 x 32 x PB  -> 13312 words = 53248 B
#define GEMM_SMEM_WORDS (2*64*PA + 2*32*PB)

// ---------------------------------------------------------------------------
// Kernel 1: qkv = x @ w_attn. CTA tile 64x128, 8 warps of 32x32, kc=32,
// cp.async double buffer, 3 CTAs/SM. Epilogue RoPE + tf32-rounded scatter.
// ---------------------------------------------------------------------------
__global__ __launch_bounds__(256, 3) void qkv_gemm_rope()
{
    extern __shared__ unsigned sm[];
    unsigned* Asb[2] = { sm,           sm + 64*PA };
    unsigned* Bsb[2] = { sm + 2*64*PA, sm + 2*64*PA + 32*PB };

    const int tid  = threadIdx.x;
    const int lane = tid & 31;
    const int w    = tid >> 5;
    const int wm   = w >> 2;        // 0..1  (32-row slabs)
    const int wn   = w & 3;         // 0..3  (32-col slabs)
    const int g    = lane >> 2;
    const int t    = lane & 3;
    const int bm   = blockIdx.y, bn = blockIdx.x;

    float acc[2][4][4];
    #pragma unroll
    for (int i = 0; i < 2; ++i)
        #pragma unroll
        for (int j = 0; j < 4; ++j)
            #pragma unroll
            for (int q = 0; q < 4; ++q) acc[i][j][q] = 0.f;

    auto load_chunk = [&](int c, int s) {
        #pragma unroll
        for (int u = 0; u < 2; ++u) {           // A: 64x32 = 512 float4
            int id  = tid + 256*u;
            int row = id >> 3, off = (id & 7) * 4;
            cp16(Asb[s] + row*PA + off,
                 g_xt + (size_t)(bm*64 + row)*NEMB + c*32 + off);
        }
        #pragma unroll
        for (int u = 0; u < 4; ++u) {           // B: 32x128 = 1024 float4
            int id  = tid + 256*u;
            int br = id >> 5, bo = (id & 31) * 4;
            cp16(Bsb[s] + br*PB + bo,
                 g_wat + (size_t)(c*32 + br)*N_QKV + bn*128 + bo);
        }
        cp_commit();
    };

    load_chunk(0, 0);
    for (int c = 0; c < NCHUNK; ++c) {
        const int s = c & 1;
        if (c + 1 < NCHUNK) { load_chunk(c+1, s^1); cp_wait<1>(); }
        else                { cp_wait<0>(); }
        __syncthreads();

        const unsigned* A = Asb[s];
        const unsigned* B = Bsb[s];
        #pragma unroll
        for (int ks = 0; ks < 4; ++ks) {
            const int kk = ks*8 + t;
            unsigned af[2][4], bf[4][2];
            #pragma unroll
            for (int mf = 0; mf < 2; ++mf) {
                int r = wm*32 + mf*16 + g;
                af[mf][0] = A[r*PA + kk];
                af[mf][1] = A[(r+8)*PA + kk];
                af[mf][2] = A[r*PA + kk + 4];
                af[mf][3] = A[(r+8)*PA + kk + 4];
            }
            #pragma unroll
            for (int nf = 0; nf < 4; ++nf) {
                int n = wn*32 + nf*8 + g;
                bf[nf][0] = B[kk*PB + n];
                bf[nf][1] = B[(kk+4)*PB + n];
            }
            #pragma unroll
            for (int mf = 0; mf < 2; ++mf)
                #pragma unroll
                for (int nf = 0; nf < 4; ++nf)
                    mma8(acc[mf][nf], af[mf], bf[nf]);
        }
        __syncthreads();
    }

    const int section = bn / 3;  // 0=q 1=k 2=v
    float* dst = (section == 0) ? g_q : (section == 1) ? g_k : g_v;
    const int ncol0 = (bn % 3) * 128;

    float invf[4];
    #pragma unroll
    for (int nf = 0; nf < 4; ++nf) {
        int d = (ncol0 + wn*32 + nf*8 + 2*t) & 63;
        invf[nf] = exp2f((float)d * (-13.287712379549449f/64.f));
    }

    #pragma unroll
    for (int mf = 0; mf < 2; ++mf) {
        #pragma unroll
        for (int half = 0; half < 2; ++half) {
            int row = bm*64 + wm*32 + mf*16 + g + 8*half;
            int b = row >> 8, tt = row & 255;
            #pragma unroll
            for (int nf = 0; nf < 4; ++nf) {
                int nn = ncol0 + wn*32 + nf*8 + 2*t;
                int h = nn >> 6, d = nn & 63;
                size_t base = (((size_t)(b*NHEAD + h))*SEQ + tt)*HD + d;
                float e = acc[mf][nf][2*half];
                float o = acc[mf][nf][2*half + 1];
                float v0, v1;
                if (section == 2) { v0 = e; v1 = o; }
                else {
                    float theta = (float)tt * invf[nf];
                    float sn, cs;
                    sincosf(theta, &sn, &cs);
                    v0 = e*cs - o*sn; v1 = o*cs + e*sn;
                }
                *(uint2*)(dst + base) = make_uint2(f2tf(v0), f2tf(v1));
            }
        }
    }
}

// ---------------------------------------------------------------------------
// Kernel 2: tensor-core causal flash attention. Heavy-half-first grid order.
// ---------------------------------------------------------------------------
#define ATTN_SMEM_WORDS (2*32*PKV + 2*32*PVV + 8*16*36)

__global__ __launch_bounds__(256) void attn_mma()
{
    extern __shared__ unsigned asm_[];
    unsigned* Ksb[2] = { asm_,            asm_ + 32*PKV };
    unsigned* Vsb[2] = { asm_ + 2*32*PKV, asm_ + 2*32*PKV + 32*PVV };
    unsigned* Ps     = asm_ + 2*32*PKV + 2*32*PVV;

    const int tid  = threadIdx.x;
    const int lane = tid & 31;
    const int w    = tid >> 5;
    const int g    = lane >> 2;
    const int t    = lane & 3;
    // heavy half (qb=1, 8 tiles) scheduled first
    const int id   = blockIdx.x;
    const int qb   = (id < BH) ? 1 : 0;
    const int bh   = (id < BH) ? id : id - BH;

    const unsigned* Qp = (const unsigned*)g_q + (size_t)bh*SEQ*HD;
    const unsigned* Kp = (const unsigned*)g_k + (size_t)bh*SEQ*HD;
    const unsigned* Vp = (const unsigned*)g_v + (size_t)bh*SEQ*HD;
    float*          Op = g_o + (size_t)bh*SEQ*HD;

    const int qrow0 = qb*128 + w*16;
    const int r0 = qrow0 + g, r1 = qrow0 + g + 8;

    unsigned qf[8][4];
    #pragma unroll
    for (int ks = 0; ks < 8; ++ks) {
        qf[ks][0] = Qp[(size_t)r0*HD + ks*8 + t];
        qf[ks][1] = Qp[(size_t)r1*HD + ks*8 + t];
        qf[ks][2] = Qp[(size_t)r0*HD + ks*8 + t + 4];
        qf[ks][3] = Qp[(size_t)r1*HD + ks*8 + t + 4];
    }

    float o[8][4];
    #pragma unroll
    for (int n = 0; n < 8; ++n)
        #pragma unroll
        for (int q = 0; q < 4; ++q) o[n][q] = 0.f;
    float m0 = -CUDART_INF_F, m1 = -CUDART_INF_F;
    float l0 = 0.f, l1 = 0.f;

    const int ntiles = qb*4 + 4;
    unsigned* Pw = Ps + w*16*36;

    auto load_tile = [&](int kt, int s) {
        #pragma unroll
        for (int u = 0; u < 2; ++u) {
            int i = tid + 256*u;
            int row = i >> 4, c4 = (i & 15) * 4;
            cp16(Ksb[s] + row*PKV + c4, Kp + (size_t)(kt*32 + row)*HD + c4);
            cp16(Vsb[s] + row*PVV + c4, Vp + (size_t)(kt*32 + row)*HD + c4);
        }
        cp_commit();
    };

    load_tile(0, 0);
    for (int kt = 0; kt < ntiles; ++kt) {
        const int s = kt & 1;
        if (kt + 1 < ntiles) { load_tile(kt+1, s^1); cp_wait<1>(); }
        else                 { cp_wait<0>(); }
        __syncthreads();

        if (kt*32 <= qrow0 + 15) {
            const unsigned* Ks = Ksb[s];
            const unsigned* Vs = Vsb[s];

            float sc[4][4];
            #pragma unroll
            for (int nt = 0; nt < 4; ++nt)
                #pragma unroll
                for (int q = 0; q < 4; ++q) sc[nt][q] = 0.f;
            #pragma unroll
            for (int ks = 0; ks < 8; ++ks) {
                #pragma unroll
                for (int nt = 0; nt < 4; ++nt) {
                    unsigned bf[2];
                    bf[0] = Ks[(nt*8 + g)*PKV + ks*8 + t];
                    bf[1] = Ks[(nt*8 + g)*PKV + ks*8 + t + 4];
                    mma8(sc[nt], qf[ks], bf);
                }
            }

            float mx0 = -CUDART_INF_F, mx1 = -CUDART_INF_F;
            #pragma unroll
            for (int nt = 0; nt < 4; ++nt) {
                int c0 = kt*32 + nt*8 + 2*t;
                sc[nt][0] = (c0     <= r0) ? sc[nt][0]*0.125f : -CUDART_INF_F;
                sc[nt][1] = (c0 + 1 <= r0) ? sc[nt][1]*0.125f : -CUDART_INF_F;
                sc[nt][2] = (c0     <= r1) ? sc[nt][2]*0.125f : -CUDART_INF_F;
                sc[nt][3] = (c0 + 1 <= r1) ? sc[nt][3]*0.125f : -CUDART_INF_F;
                mx0 = fmaxf(mx0, fmaxf(sc[nt][0], sc[nt][1]));
                mx1 = fmaxf(mx1, fmaxf(sc[nt][2], sc[nt][3]));
            }
            mx0 = fmaxf(mx0, __shfl_xor_sync(0xffffffffu, mx0, 1));
            mx0 = fmaxf(mx0, __shfl_xor_sync(0xffffffffu, mx0, 2));
            mx1 = fmaxf(mx1, __shfl_xor_sync(0xffffffffu, mx1, 1));
            mx1 = fmaxf(mx1, __shfl_xor_sync(0xffffffffu, mx1, 2));

            float mn0 = fmaxf(m0, mx0), mn1 = fmaxf(m1, mx1);
            float c0f = exp2f((m0 - mn0) * L2E);
            float c1f = exp2f((m1 - mn1) * L2E);
            m0 = mn0; m1 = mn1;

            float ps0 = 0.f, ps1 = 0.f;
            #pragma unroll
            for (int nt = 0; nt < 4; ++nt) {
                float p0 = exp2f((sc[nt][0] - m0) * L2E);
                float p1 = exp2f((sc[nt][1] - m0) * L2E);
                float p2 = exp2f((sc[nt][2] - m1) * L2E);
                float p3 = exp2f((sc[nt][3] - m1) * L2E);
                ps0 += p0 + p1;
                ps1 += p2 + p3;
                *(uint2*)(Pw + g*36 + nt*8 + 2*t)     = make_uint2(f2tf(p0), f2tf(p1));
                *(uint2*)(Pw + (g+8)*36 + nt*8 + 2*t) = make_uint2(f2tf(p2), f2tf(p3));
            }
            ps0 += __shfl_xor_sync(0xffffffffu, ps0, 1);
            ps0 += __shfl_xor_sync(0xffffffffu, ps0, 2);
            ps1 += __shfl_xor_sync(0xffffffffu, ps1, 1);
            ps1 += __shfl_xor_sync(0xffffffffu, ps1, 2);
            l0 = l0*c0f + ps0;
            l1 = l1*c1f + ps1;

            #pragma unroll
            for (int n = 0; n < 8; ++n) {
                o[n][0] *= c0f; o[n][1] *= c0f;
                o[n][2] *= c1f; o[n][3] *= c1f;
            }
            __syncwarp();

            #pragma unroll
            for (int ks = 0; ks < 4; ++ks) {
                unsigned af[4];
                af[0] = Pw[g*36 + ks*8 + t];
                af[1] = Pw[(g+8)*36 + ks*8 + t];
                af[2] = Pw[g*36 + ks*8 + t + 4];
                af[3] = Pw[(g+8)*36 + ks*8 + t + 4];
                #pragma unroll
                for (int n = 0; n < 8; ++n) {
                    unsigned bf[2];
                    bf[0] = Vs[(ks*8 + t)*PVV + n*8 + g];
                    bf[1] = Vs[(ks*8 + t + 4)*PVV + n*8 + g];
                    mma8(o[n], af, bf);
                }
            }
        }
        __syncthreads();
    }

    float i0 = 1.f / l0, i1 = 1.f / l1;
    #pragma unroll
    for (int n = 0; n < 8; ++n) {
        *(uint2*)(Op + (size_t)r0*HD + n*8 + 2*t) =
            make_uint2(f2tf(o[n][0]*i0), f2tf(o[n][1]*i0));
        *(uint2*)(Op + (size_t)r1*HD + n*8 + 2*t) =
            make_uint2(f2tf(o[n][2]*i1), f2tf(o[n][3]*i1));
    }
}

// ---------------------------------------------------------------------------
// Kernel 3: out = attn_out(gathered) @ w_proj. 64x128 tiles, 3 CTAs/SM.
// ---------------------------------------------------------------------------
__global__ __launch_bounds__(256, 3) void proj_gemm(float* __restrict__ out)
{
    extern __shared__ unsigned sm[];
    unsigned* Asb[2] = { sm,           sm + 64*PA };
    unsigned* Bsb[2] = { sm + 2*64*PA, sm + 2*64*PA + 32*PB };

    const int tid  = threadIdx.x;
    const int lane = tid & 31;
    const int w    = tid >> 5;
    const int wm   = w >> 2;
    const int wn   = w & 3;
    const int g    = lane >> 2;
    const int t    = lane & 3;
    const int bm   = blockIdx.y, bn = blockIdx.x;

    float acc[2][4][4];
    #pragma unroll
    for (int i = 0; i < 2; ++i)
        #pragma unroll
        for (int j = 0; j < 4; ++j)
            #pragma unroll
            for (int q = 0; q < 4; ++q) acc[i][j][q] = 0.f;

    auto load_chunk = [&](int c, int s) {
        #pragma unroll
        for (int u = 0; u < 2; ++u) {
            int id  = tid + 256*u;
            int row = id >> 3, off = (id & 7) * 4;
            int kk = c*32 + off;
            int h = kk >> 6, d = kk & 63;
            int m = bm*64 + row;
            int b = m >> 8, tt = m & 255;
            cp16(Asb[s] + row*PA + off,
                 g_o + (((size_t)(b*NHEAD + h))*SEQ + tt)*HD + d);
        }
        #pragma unroll
        for (int u = 0; u < 4; ++u) {
            int id  = tid + 256*u;
            int br = id >> 5, bo = (id & 31) * 4;
            cp16(Bsb[s] + br*PB + bo,
                 g_wpt + (size_t)(c*32 + br)*NEMB + bn*128 + bo);
        }
        cp_commit();
    };

    load_chunk(0, 0);
    for (int c = 0; c < NCHUNK; ++c) {
        const int s = c & 1;
        if (c + 1 < NCHUNK) { load_chunk(c+1, s^1); cp_wait<1>(); }
        else                { cp_wait<0>(); }
        __syncthreads();

        const unsigned* A = Asb[s];
        const unsigned* B = Bsb[s];
        #pragma unroll
        for (int ks = 0; ks < 4; ++ks) {
            const int kk = ks*8 + t;
            unsigned af[2][4], bf[4][2];
            #pragma unroll
            for (int mf = 0; mf < 2; ++mf) {
                int r = wm*32 + mf*16 + g;
                af[mf][0] = A[r*PA + kk];
                af[mf][1] = A[(r+8)*PA + kk];
                af[mf][2] = A[r*PA + kk + 4];
                af[mf][3] = A[(r+8)*PA + kk + 4];
            }
            #pragma unroll
            for (int nf = 0; nf < 4; ++nf) {
                int n = wn*32 + nf*8 + g;
                bf[nf][0] = B[kk*PB + n];
                bf[nf][1] = B[(kk+4)*PB + n];
            }
            #pragma unroll
            for (int mf = 0; mf < 2; ++mf)
                #pragma unroll
                for (int nf = 0; nf < 4; ++nf)
                    mma8(acc[mf][nf], af[mf], bf[nf]);
        }
        __syncthreads();
    }

    #pragma unroll
    for (int mf = 0; mf < 2; ++mf) {
        #pragma unroll
        for (int half = 0; half < 2; ++half) {
            int row = bm*64 + wm*32 + mf*16 + g + 8*half;
            #pragma unroll
            for (int nf = 0; nf < 4; ++nf) {
                int nn = bn*128 + wn*32 + nf*8 + 2*t;
                *(float2*)(out + (size_t)row*NEMB + nn) =
                    make_float2(acc[mf][nf][2*half], acc[mf][nf][2*half+1]);
            }
        }
    }
}

// ---------------------------------------------------------------------------
extern "C" void kernel_launch(void* const* d_in, const int* in_sizes, int n_in,
                              void* d_out, int out_size)
{
    const float* x      = (const float*)d_in[0];
    const float* w_attn = (const float*)d_in[1];
    const float* w_proj = (const float*)d_in[2];
    float* out = (float*)d_out;

    const int SMEM_GEMM = GEMM_SMEM_WORDS * 4;            // 53248 B
    const int SMEM_ATTN = ATTN_SMEM_WORDS * 4;            // 54272 B
    cudaFuncSetAttribute(qkv_gemm_rope,
        cudaFuncAttributeMaxDynamicSharedMemorySize, SMEM_GEMM);
    cudaFuncSetAttribute(proj_gemm,
        cudaFuncAttributeMaxDynamicSharedMemorySize, SMEM_GEMM);
    cudaFuncSetAttribute(attn_mma,
        cudaFuncAttributeMaxDynamicSharedMemorySize, SMEM_ATTN);

    const int NX4 = MTOT*NEMB/4;
    conv_tf32<<<(NX4 + 255)/256, 256>>>(x, w_attn, w_proj);

    dim3 g1(N_QKV/128, MTOT/64);    // (9, 256) = 2304 CTAs
    qkv_gemm_rope<<<g1, 256, SMEM_GEMM>>>();

    attn_mma<<<2*BH, 256, SMEM_ATTN>>>();   // heavy half first

    dim3 g3(NEMB/128, MTOT/64);     // (3, 256) = 768 CTAs
    proj_gemm<<<g3, 256, SMEM_GEMM>>>(out);
}

// round 7
// speedup vs baseline: 1.1650x; 1.1650x over previous
#include <cuda_runtime.h>
#include <math.h>
#include <math_constants.h>

// Problem constants
#define BATCH   64
#define SEQ     256
#define NEMB    384
#define NHEAD   6
#define HD      64
#define BH      (BATCH*NHEAD)      // 384
#define MTOT    (BATCH*SEQ)        // 16384
#define N_QKV   (3*NEMB)           // 1152

#define PA  36          // A smem pitch (32 + 4)
#define PB  136         // B smem pitch (128 + 8)
#define NCHUNK (NEMB/32)            // 12

#define PKV 68          // attn K pitch
#define PVV 72          // attn V pitch

#define L2E 1.4426950408889634f

// Scratch
__device__ float g_q[BH*SEQ*HD];
__device__ float g_k[BH*SEQ*HD];
__device__ float g_v[BH*SEQ*HD];
__device__ float g_o[BH*SEQ*HD];
__device__ float g_xt[MTOT*NEMB];       // tf32-rounded x
__device__ float g_wat[NEMB*N_QKV];     // tf32-rounded w_attn
__device__ float g_wpt[NEMB*NEMB];      // tf32-rounded w_proj

__device__ __forceinline__ unsigned f2tf(float f) {
    unsigned u;
    asm("cvt.rna.tf32.f32 %0, %1;" : "=r"(u) : "f"(f));
    return u;
}

__device__ __forceinline__ void mma8(float* c, const unsigned* a, const unsigned* b) {
    asm volatile(
        "mma.sync.aligned.m16n8k8.row.col.f32.tf32.tf32.f32 "
        "{%0,%1,%2,%3}, {%4,%5,%6,%7}, {%8,%9}, {%0,%1,%2,%3};"
        : "+f"(c[0]), "+f"(c[1]), "+f"(c[2]), "+f"(c[3])
        : "r"(a[0]), "r"(a[1]), "r"(a[2]), "r"(a[3]),
          "r"(b[0]), "r"(b[1]));
}

// ldmatrix on 32-bit tf32 data: b16 pair == one tf32 element; m8n8.b16 tile
// over 16B row-segments gives lane (g*4+t) element (row g, col t) -> exactly
// the tf32 mma fragment layout.
__device__ __forceinline__ void ldsm4(unsigned* r, unsigned saddr) {
    asm volatile("ldmatrix.sync.aligned.m8n8.x4.shared.b16 {%0,%1,%2,%3}, [%4];"
        : "=r"(r[0]), "=r"(r[1]), "=r"(r[2]), "=r"(r[3]) : "r"(saddr));
}
__device__ __forceinline__ void ldsm2(unsigned* r, unsigned saddr) {
    asm volatile("ldmatrix.sync.aligned.m8n8.x2.shared.b16 {%0,%1}, [%2];"
        : "=r"(r[0]), "=r"(r[1]) : "r"(saddr));
}

__device__ __forceinline__ void cp16(unsigned* dst_smem, const void* src) {
    unsigned d = (unsigned)__cvta_generic_to_shared(dst_smem);
    asm volatile("cp.async.cg.shared.global [%0], [%1], 16;\n" :: "r"(d), "l"(src));
}
__device__ __forceinline__ void cp_commit() {
    asm volatile("cp.async.commit_group;\n");
}
template <int N> __device__ __forceinline__ void cp_wait() {
    asm volatile("cp.async.wait_group %0;\n" :: "n"(N));
}

// ---------------------------------------------------------------------------
// Kernel 0: tf32-round x, w_attn, w_proj into scratch (vectorized).
// ---------------------------------------------------------------------------
__global__ __launch_bounds__(256) void conv_tf32(
    const float* __restrict__ x, const float* __restrict__ wa,
    const float* __restrict__ wp)
{
    const int i = blockIdx.x*blockDim.x + threadIdx.x;
    const int NX4 = MTOT*NEMB/4, NA4 = NEMB*N_QKV/4, NP4 = NEMB*NEMB/4;
    if (i < NX4) {
        float4 v = ((const float4*)x)[i];
        ((uint4*)g_xt)[i] = make_uint4(f2tf(v.x),f2tf(v.y),f2tf(v.z),f2tf(v.w));
    }
    if (i < NA4) {
        float4 v = ((const float4*)wa)[i];
        ((uint4*)g_wat)[i] = make_uint4(f2tf(v.x),f2tf(v.y),f2tf(v.z),f2tf(v.w));
    }
    if (i < NP4) {
        float4 v = ((const float4*)wp)[i];
        ((uint4*)g_wpt)[i] = make_uint4(f2tf(v.x),f2tf(v.y),f2tf(v.z),f2tf(v.w));
    }
}

// ---------------------------------------------------------------------------
// Kernel 1: qkv = x @ w_attn. CTA tile 128x128, 8 warps of 64x32, kc=32,
// cp.async double buffer, 2 CTAs/SM, A-fragments via ldmatrix.
// ---------------------------------------------------------------------------
__global__ __launch_bounds__(256, 2) void qkv_gemm_rope()
{
    extern __shared__ unsigned sm[];
    unsigned* Asb[2] = { sm,            sm + 128*PA };
    unsigned* Bsb[2] = { sm + 2*128*PA, sm + 2*128*PA + 32*PB };
    const unsigned sm_u32 = (unsigned)__cvta_generic_to_shared(sm);
    const unsigned Au[2] = { sm_u32, sm_u32 + 128*PA*4u };

    const int tid  = threadIdx.x;
    const int lane = tid & 31;
    const int w    = tid >> 5;
    const int wm   = w >> 2;
    const int wn   = w & 3;
    const int g    = lane >> 2;
    const int t    = lane & 3;
    const int lrow = lane & 15;              // ldmatrix row supplier
    const int lcol = ((lane >> 4) & 1) * 4;  // ldmatrix col-half supplier
    const int bm   = blockIdx.y, bn = blockIdx.x;

    float acc[4][4][4];
    #pragma unroll
    for (int i = 0; i < 4; ++i)
        #pragma unroll
        for (int j = 0; j < 4; ++j)
            #pragma unroll
            for (int q = 0; q < 4; ++q) acc[i][j][q] = 0.f;

    auto load_chunk = [&](int c, int s) {
        #pragma unroll
        for (int u = 0; u < 4; ++u) {
            int id  = tid + 256*u;
            int row = id >> 3, off = (id & 7) * 4;
            cp16(Asb[s] + row*PA + off,
                 g_xt + (size_t)(bm*128 + row)*NEMB + c*32 + off);
            int br = id >> 5, bo = (id & 31) * 4;
            cp16(Bsb[s] + br*PB + bo,
                 g_wat + (size_t)(c*32 + br)*N_QKV + bn*128 + bo);
        }
        cp_commit();
    };

    load_chunk(0, 0);
    for (int c = 0; c < NCHUNK; ++c) {
        const int s = c & 1;
        if (c + 1 < NCHUNK) { load_chunk(c+1, s^1); cp_wait<1>(); }
        else                { cp_wait<0>(); }
        __syncthreads();

        const unsigned* B = Bsb[s];
        #pragma unroll
        for (int ks = 0; ks < 4; ++ks) {
            const int kk = ks*8 + t;
            unsigned af[4][4], bf[4][2];
            #pragma unroll
            for (int mf = 0; mf < 4; ++mf) {
                unsigned addr = Au[s] +
                    (((wm*64 + mf*16 + lrow)*PA + ks*8 + lcol) << 2);
                ldsm4(af[mf], addr);
            }
            #pragma unroll
            for (int nf = 0; nf < 4; ++nf) {
                int n = wn*32 + nf*8 + g;
                bf[nf][0] = B[kk*PB + n];
                bf[nf][1] = B[(kk+4)*PB + n];
            }
            #pragma unroll
            for (int mf = 0; mf < 4; ++mf)
                #pragma unroll
                for (int nf = 0; nf < 4; ++nf)
                    mma8(acc[mf][nf], af[mf], bf[nf]);
        }
        __syncthreads();
    }

    const int section = bn / 3;  // 0=q 1=k 2=v
    float* dst = (section == 0) ? g_q : (section == 1) ? g_k : g_v;
    const int ncol0 = (bn % 3) * 128;

    float invf[4];
    #pragma unroll
    for (int nf = 0; nf < 4; ++nf) {
        int d = (ncol0 + wn*32 + nf*8 + 2*t) & 63;
        invf[nf] = exp2f((float)d * (-13.287712379549449f/64.f));
    }

    #pragma unroll
    for (int mf = 0; mf < 4; ++mf) {
        int r0 = bm*128 + wm*64 + mf*16 + g;
        #pragma unroll
        for (int half = 0; half < 2; ++half) {
            int row = r0 + 8*half;
            int b = row >> 8, tt = row & 255;
            #pragma unroll
            for (int nf = 0; nf < 4; ++nf) {
                int nn = ncol0 + wn*32 + nf*8 + 2*t;
                int h = nn >> 6, d = nn & 63;
                size_t base = (((size_t)(b*NHEAD + h))*SEQ + tt)*HD + d;
                float e = acc[mf][nf][2*half];
                float o = acc[mf][nf][2*half + 1];
                float v0, v1;
                if (section == 2) { v0 = e; v1 = o; }
                else {
                    float theta = (float)tt * invf[nf];
                    float sn, cs;
                    sincosf(theta, &sn, &cs);
                    v0 = e*cs - o*sn; v1 = o*cs + e*sn;
                }
                *(uint2*)(dst + base) = make_uint2(f2tf(v0), f2tf(v1));
            }
        }
    }
}

// ---------------------------------------------------------------------------
// Kernel 2: tensor-core causal flash attention; K and P fragments via
// ldmatrix. Heavy-half-first grid order.
// ---------------------------------------------------------------------------
#define ATTN_SMEM_WORDS (2*32*PKV + 2*32*PVV + 8*16*36)

__global__ __launch_bounds__(256) void attn_mma()
{
    extern __shared__ unsigned asm_[];
    unsigned* Ksb[2] = { asm_,            asm_ + 32*PKV };
    unsigned* Vsb[2] = { asm_ + 2*32*PKV, asm_ + 2*32*PKV + 32*PVV };
    unsigned* Ps     = asm_ + 2*32*PKV + 2*32*PVV;
    const unsigned sm_u32 = (unsigned)__cvta_generic_to_shared(asm_);
    const unsigned Ku[2]  = { sm_u32, sm_u32 + 32*PKV*4u };

    const int tid  = threadIdx.x;
    const int lane = tid & 31;
    const int w    = tid >> 5;
    const int g    = lane >> 2;
    const int t    = lane & 3;
    const int lrow = lane & 15;
    const int lcol = ((lane >> 4) & 1) * 4;
    const int krow8 = lane & 7;
    const int kcol4 = ((lane >> 3) & 1) * 4;
    // heavy half (qb=1, 8 tiles) scheduled first
    const int id   = blockIdx.x;
    const int qb   = (id < BH) ? 1 : 0;
    const int bh   = (id < BH) ? id : id - BH;

    const unsigned* Qp = (const unsigned*)g_q + (size_t)bh*SEQ*HD;
    const unsigned* Kp = (const unsigned*)g_k + (size_t)bh*SEQ*HD;
    const unsigned* Vp = (const unsigned*)g_v + (size_t)bh*SEQ*HD;
    float*          Op = g_o + (size_t)bh*SEQ*HD;

    const int qrow0 = qb*128 + w*16;
    const int r0 = qrow0 + g, r1 = qrow0 + g + 8;

    unsigned qf[8][4];
    #pragma unroll
    for (int ks = 0; ks < 8; ++ks) {
        qf[ks][0] = Qp[(size_t)r0*HD + ks*8 + t];
        qf[ks][1] = Qp[(size_t)r1*HD + ks*8 + t];
        qf[ks][2] = Qp[(size_t)r0*HD + ks*8 + t + 4];
        qf[ks][3] = Qp[(size_t)r1*HD + ks*8 + t + 4];
    }

    float o[8][4];
    #pragma unroll
    for (int n = 0; n < 8; ++n)
        #pragma unroll
        for (int q = 0; q < 4; ++q) o[n][q] = 0.f;
    float m0 = -CUDART_INF_F, m1 = -CUDART_INF_F;
    float l0 = 0.f, l1 = 0.f;

    const int ntiles = qb*4 + 4;
    unsigned* Pw = Ps + w*16*36;
    const unsigned Pw_u32 = sm_u32 + (2*32*PKV + 2*32*PVV + w*16*36) * 4u;

    auto load_tile = [&](int kt, int s) {
        #pragma unroll
        for (int u = 0; u < 2; ++u) {
            int i = tid + 256*u;
            int row = i >> 4, c4 = (i & 15) * 4;
            cp16(Ksb[s] + row*PKV + c4, Kp + (size_t)(kt*32 + row)*HD + c4);
            cp16(Vsb[s] + row*PVV + c4, Vp + (size_t)(kt*32 + row)*HD + c4);
        }
        cp_commit();
    };

    load_tile(0, 0);
    for (int kt = 0; kt < ntiles; ++kt) {
        const int s = kt & 1;
        if (kt + 1 < ntiles) { load_tile(kt+1, s^1); cp_wait<1>(); }
        else                 { cp_wait<0>(); }
        __syncthreads();

        if (kt*32 <= qrow0 + 15) {
            const unsigned* Vs = Vsb[s];

            float sc[4][4];
            #pragma unroll
            for (int nt = 0; nt < 4; ++nt)
                #pragma unroll
                for (int q = 0; q < 4; ++q) sc[nt][q] = 0.f;
            #pragma unroll
            for (int ks = 0; ks < 8; ++ks) {
                #pragma unroll
                for (int nt = 0; nt < 4; ++nt) {
                    unsigned bf[2];
                    ldsm2(bf, Ku[s] +
                        (((nt*8 + krow8)*PKV + ks*8 + kcol4) << 2));
                    mma8(sc[nt], qf[ks], bf);
                }
            }

            float mx0 = -CUDART_INF_F, mx1 = -CUDART_INF_F;
            #pragma unroll
            for (int nt = 0; nt < 4; ++nt) {
                int c0 = kt*32 + nt*8 + 2*t;
                sc[nt][0] = (c0     <= r0) ? sc[nt][0]*0.125f : -CUDART_INF_F;
                sc[nt][1] = (c0 + 1 <= r0) ? sc[nt][1]*0.125f : -CUDART_INF_F;
                sc[nt][2] = (c0     <= r1) ? sc[nt][2]*0.125f : -CUDART_INF_F;
                sc[nt][3] = (c0 + 1 <= r1) ? sc[nt][3]*0.125f : -CUDART_INF_F;
                mx0 = fmaxf(mx0, fmaxf(sc[nt][0], sc[nt][1]));
                mx1 = fmaxf(mx1, fmaxf(sc[nt][2], sc[nt][3]));
            }
            mx0 = fmaxf(mx0, __shfl_xor_sync(0xffffffffu, mx0, 1));
            mx0 = fmaxf(mx0, __shfl_xor_sync(0xffffffffu, mx0, 2));
            mx1 = fmaxf(mx1, __shfl_xor_sync(0xffffffffu, mx1, 1));
            mx1 = fmaxf(mx1, __shfl_xor_sync(0xffffffffu, mx1, 2));

            float mn0 = fmaxf(m0, mx0), mn1 = fmaxf(m1, mx1);
            float c0f = exp2f((m0 - mn0) * L2E);
            float c1f = exp2f((m1 - mn1) * L2E);
            m0 = mn0; m1 = mn1;

            float ps0 = 0.f, ps1 = 0.f;
            #pragma unroll
            for (int nt = 0; nt < 4; ++nt) {
                float p0 = exp2f((sc[nt][0] - m0) * L2E);
                float p1 = exp2f((sc[nt][1] - m0) * L2E);
                float p2 = exp2f((sc[nt][2] - m1) * L2E);
                float p3 = exp2f((sc[nt][3] - m1) * L2E);
                ps0 += p0 + p1;
                ps1 += p2 + p3;
                *(uint2*)(Pw + g*36 + nt*8 + 2*t)     = make_uint2(f2tf(p0), f2tf(p1));
                *(uint2*)(Pw + (g+8)*36 + nt*8 + 2*t) = make_uint2(f2tf(p2), f2tf(p3));
            }
            ps0 += __shfl_xor_sync(0xffffffffu, ps0, 1);
            ps0 += __shfl_xor_sync(0xffffffffu, ps0, 2);
            ps1 += __shfl_xor_sync(0xffffffffu, ps1, 1);
            ps1 += __shfl_xor_sync(0xffffffffu, ps1, 2);
            l0 = l0*c0f + ps0;
            l1 = l1*c1f + ps1;

            #pragma unroll
            for (int n = 0; n < 8; ++n) {
                o[n][0] *= c0f; o[n][1] *= c0f;
                o[n][2] *= c1f; o[n][3] *= c1f;
            }
            __syncwarp();

            #pragma unroll
            for (int ks = 0; ks < 4; ++ks) {
                unsigned af[4];
                ldsm4(af, Pw_u32 + ((lrow*36 + ks*8 + lcol) << 2));
                #pragma unroll
                for (int n = 0; n < 8; ++n) {
                    unsigned bf[2];
                    bf[0] = Vs[(ks*8 + t)*PVV + n*8 + g];
                    bf[1] = Vs[(ks*8 + t + 4)*PVV + n*8 + g];
                    mma8(o[n], af, bf);
                }
            }
        }
        __syncthreads();
    }

    float i0 = 1.f / l0, i1 = 1.f / l1;
    #pragma unroll
    for (int n = 0; n < 8; ++n) {
        *(uint2*)(Op + (size_t)r0*HD + n*8 + 2*t) =
            make_uint2(f2tf(o[n][0]*i0), f2tf(o[n][1]*i0));
        *(uint2*)(Op + (size_t)r1*HD + n*8 + 2*t) =
            make_uint2(f2tf(o[n][2]*i1), f2tf(o[n][3]*i1));
    }
}

// ---------------------------------------------------------------------------
// Kernel 3: out = attn_out(gathered) @ w_proj. Same 128x128 config.
// ---------------------------------------------------------------------------
__global__ __launch_bounds__(256, 2) void proj_gemm(float* __restrict__ out)
{
    extern __shared__ unsigned sm[];
    unsigned* Asb[2] = { sm,            sm + 128*PA };
    unsigned* Bsb[2] = { sm + 2*128*PA, sm + 2*128*PA + 32*PB };
    const unsigned sm_u32 = (unsigned)__cvta_generic_to_shared(sm);
    const unsigned Au[2] = { sm_u32, sm_u32 + 128*PA*4u };

    const int tid  = threadIdx.x;
    const int lane = tid & 31;
    const int w    = tid >> 5;
    const int wm   = w >> 2;
    const int wn   = w & 3;
    const int g    = lane >> 2;
    const int t    = lane & 3;
    const int lrow = lane & 15;
    const int lcol = ((lane >> 4) & 1) * 4;
    const int bm   = blockIdx.y, bn = blockIdx.x;

    float acc[4][4][4];
    #pragma unroll
    for (int i = 0; i < 4; ++i)
        #pragma unroll
        for (int j = 0; j < 4; ++j)
            #pragma unroll
            for (int q = 0; q < 4; ++q) acc[i][j][q] = 0.f;

    auto load_chunk = [&](int c, int s) {
        #pragma unroll
        for (int u = 0; u < 4; ++u) {
            int id  = tid + 256*u;
            int row = id >> 3, off = (id & 7) * 4;
            int kk = c*32 + off;
            int h = kk >> 6, d = kk & 63;
            int m = bm*128 + row;
            int b = m >> 8, tt = m & 255;
            cp16(Asb[s] + row*PA + off,
                 g_o + (((size_t)(b*NHEAD + h))*SEQ + tt)*HD + d);
            int br = id >> 5, bo = (id & 31) * 4;
            cp16(Bsb[s] + br*PB + bo,
                 g_wpt + (size_t)(c*32 + br)*NEMB + bn*128 + bo);
        }
        cp_commit();
    };

    load_chunk(0, 0);
    for (int c = 0; c < NCHUNK; ++c) {
        const int s = c & 1;
        if (c + 1 < NCHUNK) { load_chunk(c+1, s^1); cp_wait<1>(); }
        else                { cp_wait<0>(); }
        __syncthreads();

        const unsigned* B = Bsb[s];
        #pragma unroll
        for (int ks = 0; ks < 4; ++ks) {
            const int kk = ks*8 + t;
            unsigned af[4][4], bf[4][2];
            #pragma unroll
            for (int mf = 0; mf < 4; ++mf) {
                unsigned addr = Au[s] +
                    (((wm*64 + mf*16 + lrow)*PA + ks*8 + lcol) << 2);
                ldsm4(af[mf], addr);
            }
            #pragma unroll
            for (int nf = 0; nf < 4; ++nf) {
                int n = wn*32 + nf*8 + g;
                bf[nf][0] = B[kk*PB + n];
                bf[nf][1] = B[(kk+4)*PB + n];
            }
            #pragma unroll
            for (int mf = 0; mf < 4; ++mf)
                #pragma unroll
                for (int nf = 0; nf < 4; ++nf)
                    mma8(acc[mf][nf], af[mf], bf[nf]);
        }
        __syncthreads();
    }

    #pragma unroll
    for (int mf = 0; mf < 4; ++mf) {
        int r0 = bm*128 + wm*64 + mf*16 + g;
        #pragma unroll
        for (int half = 0; half < 2; ++half) {
            int row = r0 + 8*half;
            #pragma unroll
            for (int nf = 0; nf < 4; ++nf) {
                int nn = bn*128 + wn*32 + nf*8 + 2*t;
                *(float2*)(out + (size_t)row*NEMB + nn) =
                    make_float2(acc[mf][nf][2*half], acc[mf][nf][2*half+1]);
            }
        }
    }
}

// ---------------------------------------------------------------------------
extern "C" void kernel_launch(void* const* d_in, const int* in_sizes, int n_in,
                              void* d_out, int out_size)
{
    const float* x      = (const float*)d_in[0];
    const float* w_attn = (const float*)d_in[1];
    const float* w_proj = (const float*)d_in[2];
    float* out = (float*)d_out;

    const int SMEM_GEMM = (2*128*PA + 2*32*PB) * 4;      // 71680 B
    const int SMEM_ATTN = ATTN_SMEM_WORDS * 4;            // 54272 B
    cudaFuncSetAttribute(qkv_gemm_rope,
        cudaFuncAttributeMaxDynamicSharedMemorySize, SMEM_GEMM);
    cudaFuncSetAttribute(proj_gemm,
        cudaFuncAttributeMaxDynamicSharedMemorySize, SMEM_GEMM);
    cudaFuncSetAttribute(attn_mma,
        cudaFuncAttributeMaxDynamicSharedMemorySize, SMEM_ATTN);

    const int NX4 = MTOT*NEMB/4;
    conv_tf32<<<(NX4 + 255)/256, 256>>>(x, w_attn, w_proj);

    dim3 g1(N_QKV/128, MTOT/128);   // (9, 128)
    qkv_gemm_rope<<<g1, 256, SMEM_GEMM>>>();

    attn_mma<<<2*BH, 256, SMEM_ATTN>>>();   // heavy half first

    dim3 g3(NEMB/128, MTOT/128);    // (3, 128)
    proj_gemm<<<g3, 256, SMEM_GEMM>>>(out);
}

// round 8
// speedup vs baseline: 1.2170x; 1.0446x over previous
#include <cuda_runtime.h>
#include <math.h>
#include <math_constants.h>

// Problem constants
#define BATCH   64
#define SEQ     256
#define NEMB    384
#define NHEAD   6
#define HD      64
#define BH      (BATCH*NHEAD)      // 384
#define MTOT    (BATCH*SEQ)        // 16384
#define N_QKV   (3*NEMB)           // 1152

#define PA  36          // smem pitch for 32-wide k tiles (32 + 4)
#define NCHUNK (NEMB/32)            // 12

#define PKV 68          // attn K pitch ([key][hd] rows)
#define PVT 36          // attn V^T pitch ([hd][key] rows)

#define L2E 1.4426950408889634f

// Scratch
__device__ float g_q[BH*SEQ*HD];        // [bh][T][hd]
__device__ float g_k[BH*SEQ*HD];        // [bh][T][hd]
__device__ float g_v[BH*SEQ*HD];        // [bh][hd][T]  (TRANSPOSED)
__device__ float g_o[BH*SEQ*HD];        // [bh][T][hd]
__device__ float g_xt[MTOT*NEMB];       // tf32-rounded x
__device__ float g_watT[N_QKV*NEMB];    // tf32-rounded w_attn^T  [N][K]
__device__ float g_wptT[NEMB*NEMB];     // tf32-rounded w_proj^T  [N][K]

__device__ __forceinline__ unsigned f2tf(float f) {
    unsigned u;
    asm("cvt.rna.tf32.f32 %0, %1;" : "=r"(u) : "f"(f));
    return u;
}

__device__ __forceinline__ void mma8(float* c, const unsigned* a, const unsigned* b) {
    asm volatile(
        "mma.sync.aligned.m16n8k8.row.col.f32.tf32.tf32.f32 "
        "{%0,%1,%2,%3}, {%4,%5,%6,%7}, {%8,%9}, {%0,%1,%2,%3};"
        : "+f"(c[0]), "+f"(c[1]), "+f"(c[2]), "+f"(c[3])
        : "r"(a[0]), "r"(a[1]), "r"(a[2]), "r"(a[3]),
          "r"(b[0]), "r"(b[1]));
}

__device__ __forceinline__ void ldsm4(unsigned* r, unsigned saddr) {
    asm volatile("ldmatrix.sync.aligned.m8n8.x4.shared.b16 {%0,%1,%2,%3}, [%4];"
        : "=r"(r[0]), "=r"(r[1]), "=r"(r[2]), "=r"(r[3]) : "r"(saddr));
}

__device__ __forceinline__ void cp16(unsigned* dst_smem, const void* src) {
    unsigned d = (unsigned)__cvta_generic_to_shared(dst_smem);
    asm volatile("cp.async.cg.shared.global [%0], [%1], 16;\n" :: "r"(d), "l"(src));
}
__device__ __forceinline__ void cp_commit() {
    asm volatile("cp.async.commit_group;\n");
}
template <int N> __device__ __forceinline__ void cp_wait() {
    asm volatile("cp.async.wait_group %0;\n" :: "n"(N));
}

// ---------------------------------------------------------------------------
// Kernel 0: tf32-round x; round+TRANSPOSE w_attn, w_proj.
// ---------------------------------------------------------------------------
__global__ __launch_bounds__(256) void conv_tf32(
    const float* __restrict__ x, const float* __restrict__ wa,
    const float* __restrict__ wp)
{
    const int i = blockIdx.x*blockDim.x + threadIdx.x;
    const int NX4 = MTOT*NEMB/4;
    if (i < NX4) {
        float4 v = ((const float4*)x)[i];
        ((uint4*)g_xt)[i] = make_uint4(f2tf(v.x),f2tf(v.y),f2tf(v.z),f2tf(v.w));
    }
    if (i < NEMB*N_QKV) {               // coalesced read, strided write
        int k = i / N_QKV, n = i % N_QKV;
        ((unsigned*)g_watT)[n*NEMB + k] = f2tf(wa[i]);
    }
    if (i < NEMB*NEMB) {
        int k = i / NEMB, n = i % NEMB;
        ((unsigned*)g_wptT)[n*NEMB + k] = f2tf(wp[i]);
    }
}

// GEMM smem: A 2 x 128 x PA + B 2 x 128 x PA = 18432 words = 73728 B
#define GEMM_SMEM_WORDS (4*128*PA)

// ---------------------------------------------------------------------------
// Kernel 1: qkv = x @ w_attn. 128x128 tile, 8 warps of 64x32, kc=32,
// cp.async double buffer, all fragments via ldmatrix.
// ---------------------------------------------------------------------------
__global__ __launch_bounds__(256, 2) void qkv_gemm_rope()
{
    extern __shared__ unsigned sm[];
    unsigned* Asb[2] = { sm,            sm + 128*PA };
    unsigned* Bsb[2] = { sm + 2*128*PA, sm + 3*128*PA };
    const unsigned sm_u32 = (unsigned)__cvta_generic_to_shared(sm);
    const unsigned Au[2] = { sm_u32,                sm_u32 + 128*PA*4u };
    const unsigned Bu[2] = { sm_u32 + 2*128*PA*4u,  sm_u32 + 3*128*PA*4u };

    const int tid  = threadIdx.x;
    const int lane = tid & 31;
    const int w    = tid >> 5;
    const int wm   = w >> 2;
    const int wn   = w & 3;
    const int g    = lane >> 2;
    const int t    = lane & 3;
    const int lrow = lane & 15;              // A-ldsm supplier
    const int lcol = ((lane >> 4) & 1) * 4;
    const int l8   = lane & 7;               // B-ldsm suppliers
    const int lq   = ((lane >> 3) & 1) * 4;  // k-half
    const int lh   = (lane >> 4) & 1;        // tile-pair half
    const int bm   = blockIdx.y, bn = blockIdx.x;

    float acc[4][4][4];
    #pragma unroll
    for (int i = 0; i < 4; ++i)
        #pragma unroll
        for (int j = 0; j < 4; ++j)
            #pragma unroll
            for (int q = 0; q < 4; ++q) acc[i][j][q] = 0.f;

    auto load_chunk = [&](int c, int s) {
        #pragma unroll
        for (int u = 0; u < 4; ++u) {
            int id  = tid + 256*u;
            int row = id >> 3, off = (id & 7) * 4;
            cp16(Asb[s] + row*PA + off,
                 g_xt + (size_t)(bm*128 + row)*NEMB + c*32 + off);
            cp16(Bsb[s] + row*PA + off,
                 g_watT + (size_t)(bn*128 + row)*NEMB + c*32 + off);
        }
        cp_commit();
    };

    load_chunk(0, 0);
    for (int c = 0; c < NCHUNK; ++c) {
        const int s = c & 1;
        if (c + 1 < NCHUNK) { load_chunk(c+1, s^1); cp_wait<1>(); }
        else                { cp_wait<0>(); }
        __syncthreads();

        #pragma unroll
        for (int ks = 0; ks < 4; ++ks) {
            unsigned af[4][4], bf[2][4];
            #pragma unroll
            for (int mf = 0; mf < 4; ++mf)
                ldsm4(af[mf], Au[s] +
                    (((wm*64 + mf*16 + lrow)*PA + ks*8 + lcol) << 2));
            #pragma unroll
            for (int nb = 0; nb < 2; ++nb)   // covers nf = 2nb, 2nb+1
                ldsm4(bf[nb], Bu[s] +
                    (((wn*32 + (nb*2 + lh)*8 + l8)*PA + ks*8 + lq) << 2));
            #pragma unroll
            for (int mf = 0; mf < 4; ++mf)
                #pragma unroll
                for (int nf = 0; nf < 4; ++nf)
                    mma8(acc[mf][nf], af[mf], bf[nf>>1] + (nf&1)*2);
        }
        __syncthreads();
    }

    const int section = bn / 3;  // 0=q 1=k 2=v
    const int ncol0 = (bn % 3) * 128;

    float invf[4];
    #pragma unroll
    for (int nf = 0; nf < 4; ++nf) {
        int d = (ncol0 + wn*32 + nf*8 + 2*t) & 63;
        invf[nf] = exp2f((float)d * (-13.287712379549449f/64.f));
    }

    #pragma unroll
    for (int mf = 0; mf < 4; ++mf) {
        int r0 = bm*128 + wm*64 + mf*16 + g;
        #pragma unroll
        for (int half = 0; half < 2; ++half) {
            int row = r0 + 8*half;
            int b = row >> 8, tt = row & 255;
            #pragma unroll
            for (int nf = 0; nf < 4; ++nf) {
                int nn = ncol0 + wn*32 + nf*8 + 2*t;
                int h = nn >> 6, d = nn & 63;
                float e = acc[mf][nf][2*half];
                float o = acc[mf][nf][2*half + 1];
                if (section == 2) {
                    // V stored transposed: [bh][hd][T]
                    size_t base = ((size_t)(b*NHEAD + h)*HD + d)*SEQ + tt;
                    ((unsigned*)g_v)[base]       = f2tf(e);
                    ((unsigned*)g_v)[base + SEQ] = f2tf(o);
                } else {
                    float theta = (float)tt * invf[nf];
                    float sn, cs;
                    sincosf(theta, &sn, &cs);
                    float v0 = e*cs - o*sn, v1 = o*cs + e*sn;
                    float* dst = (section == 0) ? g_q : g_k;
                    size_t base = (((size_t)(b*NHEAD + h))*SEQ + tt)*HD + d;
                    *(uint2*)(dst + base) = make_uint2(f2tf(v0), f2tf(v1));
                }
            }
        }
    }
}

// ---------------------------------------------------------------------------
// Kernel 2: tensor-core causal flash attention; K, V^T, P fragments all via
// ldmatrix x4. Heavy-half-first grid order.
// ---------------------------------------------------------------------------
#define ATTN_SMEM_WORDS (2*32*PKV + 2*64*PVT + 8*16*36)

__global__ __launch_bounds__(256) void attn_mma()
{
    extern __shared__ unsigned asm_[];
    unsigned* Ksb[2] = { asm_,            asm_ + 32*PKV };
    unsigned* Vsb[2] = { asm_ + 2*32*PKV, asm_ + 2*32*PKV + 64*PVT };
    unsigned* Ps     = asm_ + 2*32*PKV + 2*64*PVT;
    const unsigned sm_u32 = (unsigned)__cvta_generic_to_shared(asm_);
    const unsigned Ku[2]  = { sm_u32, sm_u32 + 32*PKV*4u };
    const unsigned Vu[2]  = { sm_u32 + 2*32*PKV*4u,
                              sm_u32 + (2*32*PKV + 64*PVT)*4u };

    const int tid  = threadIdx.x;
    const int lane = tid & 31;
    const int w    = tid >> 5;
    const int g    = lane >> 2;
    const int t    = lane & 3;
    const int lrow = lane & 15;
    const int lcol = ((lane >> 4) & 1) * 4;
    const int l8   = lane & 7;
    const int lq   = ((lane >> 3) & 1) * 4;
    const int lh   = (lane >> 4) & 1;
    // heavy half (qb=1, 8 tiles) scheduled first
    const int id   = blockIdx.x;
    const int qb   = (id < BH) ? 1 : 0;
    const int bh   = (id < BH) ? id : id - BH;

    const unsigned* Qp = (const unsigned*)g_q + (size_t)bh*SEQ*HD;
    const unsigned* Kp = (const unsigned*)g_k + (size_t)bh*SEQ*HD;
    const unsigned* Vp = (const unsigned*)g_v + (size_t)bh*HD*SEQ;  // [hd][T]
    float*          Op = g_o + (size_t)bh*SEQ*HD;

    const int qrow0 = qb*128 + w*16;
    const int r0 = qrow0 + g, r1 = qrow0 + g + 8;

    unsigned qf[8][4];
    #pragma unroll
    for (int ks = 0; ks < 8; ++ks) {
        qf[ks][0] = Qp[(size_t)r0*HD + ks*8 + t];
        qf[ks][1] = Qp[(size_t)r1*HD + ks*8 + t];
        qf[ks][2] = Qp[(size_t)r0*HD + ks*8 + t + 4];
        qf[ks][3] = Qp[(size_t)r1*HD + ks*8 + t + 4];
    }

    float o[8][4];
    #pragma unroll
    for (int n = 0; n < 8; ++n)
        #pragma unroll
        for (int q = 0; q < 4; ++q) o[n][q] = 0.f;
    float m0 = -CUDART_INF_F, m1 = -CUDART_INF_F;
    float l0 = 0.f, l1 = 0.f;

    const int ntiles = qb*4 + 4;
    unsigned* Pw = Ps + w*16*36;
    const unsigned Pw_u32 = sm_u32 + (2*32*PKV + 2*64*PVT + w*16*36) * 4u;

    auto load_tile = [&](int kt, int s) {
        #pragma unroll
        for (int u = 0; u < 2; ++u) {
            int i = tid + 256*u;
            int krow = i >> 4, kc4 = (i & 15) * 4;      // K: 32 rows x 64
            cp16(Ksb[s] + krow*PKV + kc4,
                 Kp + (size_t)(kt*32 + krow)*HD + kc4);
            int vrow = i >> 3, vc4 = (i & 7) * 4;       // V^T: 64 rows x 32
            cp16(Vsb[s] + vrow*PVT + vc4,
                 Vp + (size_t)vrow*SEQ + kt*32 + vc4);
        }
        cp_commit();
    };

    load_tile(0, 0);
    for (int kt = 0; kt < ntiles; ++kt) {
        const int s = kt & 1;
        if (kt + 1 < ntiles) { load_tile(kt+1, s^1); cp_wait<1>(); }
        else                 { cp_wait<0>(); }
        __syncthreads();

        if (kt*32 <= qrow0 + 15) {
            float sc[4][4];
            #pragma unroll
            for (int nt = 0; nt < 4; ++nt)
                #pragma unroll
                for (int q = 0; q < 4; ++q) sc[nt][q] = 0.f;
            #pragma unroll
            for (int ks = 0; ks < 8; ++ks) {
                #pragma unroll
                for (int nb = 0; nb < 2; ++nb) {   // nt = 2nb, 2nb+1
                    unsigned bf[4];
                    ldsm4(bf, Ku[s] +
                        ((((nb*2 + lh)*8 + l8)*PKV + ks*8 + lq) << 2));
                    mma8(sc[nb*2],     qf[ks], bf);
                    mma8(sc[nb*2 + 1], qf[ks], bf + 2);
                }
            }

            float mx0 = -CUDART_INF_F, mx1 = -CUDART_INF_F;
            #pragma unroll
            for (int nt = 0; nt < 4; ++nt) {
                int c0 = kt*32 + nt*8 + 2*t;
                sc[nt][0] = (c0     <= r0) ? sc[nt][0]*0.125f : -CUDART_INF_F;
                sc[nt][1] = (c0 + 1 <= r0) ? sc[nt][1]*0.125f : -CUDART_INF_F;
                sc[nt][2] = (c0     <= r1) ? sc[nt][2]*0.125f : -CUDART_INF_F;
                sc[nt][3] = (c0 + 1 <= r1) ? sc[nt][3]*0.125f : -CUDART_INF_F;
                mx0 = fmaxf(mx0, fmaxf(sc[nt][0], sc[nt][1]));
                mx1 = fmaxf(mx1, fmaxf(sc[nt][2], sc[nt][3]));
            }
            mx0 = fmaxf(mx0, __shfl_xor_sync(0xffffffffu, mx0, 1));
            mx0 = fmaxf(mx0, __shfl_xor_sync(0xffffffffu, mx0, 2));
            mx1 = fmaxf(mx1, __shfl_xor_sync(0xffffffffu, mx1, 1));
            mx1 = fmaxf(mx1, __shfl_xor_sync(0xffffffffu, mx1, 2));

            float mn0 = fmaxf(m0, mx0), mn1 = fmaxf(m1, mx1);
            float c0f = exp2f((m0 - mn0) * L2E);
            float c1f = exp2f((m1 - mn1) * L2E);
            m0 = mn0; m1 = mn1;

            float ps0 = 0.f, ps1 = 0.f;
            #pragma unroll
            for (int nt = 0; nt < 4; ++nt) {
                float p0 = exp2f((sc[nt][0] - m0) * L2E);
                float p1 = exp2f((sc[nt][1] - m0) * L2E);
                float p2 = exp2f((sc[nt][2] - m1) * L2E);
                float p3 = exp2f((sc[nt][3] - m1) * L2E);
                ps0 += p0 + p1;
                ps1 += p2 + p3;
                *(uint2*)(Pw + g*36 + nt*8 + 2*t)     = make_uint2(f2tf(p0), f2tf(p1));
                *(uint2*)(Pw + (g+8)*36 + nt*8 + 2*t) = make_uint2(f2tf(p2), f2tf(p3));
            }
            ps0 += __shfl_xor_sync(0xffffffffu, ps0, 1);
            ps0 += __shfl_xor_sync(0xffffffffu, ps0, 2);
            ps1 += __shfl_xor_sync(0xffffffffu, ps1, 1);
            ps1 += __shfl_xor_sync(0xffffffffu, ps1, 2);
            l0 = l0*c0f + ps0;
            l1 = l1*c1f + ps1;

            #pragma unroll
            for (int n = 0; n < 8; ++n) {
                o[n][0] *= c0f; o[n][1] *= c0f;
                o[n][2] *= c1f; o[n][3] *= c1f;
            }
            __syncwarp();

            #pragma unroll
            for (int ks = 0; ks < 4; ++ks) {
                unsigned af[4];
                ldsm4(af, Pw_u32 + ((lrow*36 + ks*8 + lcol) << 2));
                #pragma unroll
                for (int nb = 0; nb < 4; ++nb) {   // n = 2nb, 2nb+1
                    unsigned bf[4];
                    ldsm4(bf, Vu[s] +
                        ((((nb*2 + lh)*8 + l8)*PVT + ks*8 + lq) << 2));
                    mma8(o[nb*2],     af, bf);
                    mma8(o[nb*2 + 1], af, bf + 2);
                }
            }
        }
        __syncthreads();
    }

    float i0 = 1.f / l0, i1 = 1.f / l1;
    #pragma unroll
    for (int n = 0; n < 8; ++n) {
        *(uint2*)(Op + (size_t)r0*HD + n*8 + 2*t) =
            make_uint2(f2tf(o[n][0]*i0), f2tf(o[n][1]*i0));
        *(uint2*)(Op + (size_t)r1*HD + n*8 + 2*t) =
            make_uint2(f2tf(o[n][2]*i1), f2tf(o[n][3]*i1));
    }
}

// ---------------------------------------------------------------------------
// Kernel 3: out = attn_out(gathered) @ w_proj. All-ldmatrix fragments.
// ---------------------------------------------------------------------------
__global__ __launch_bounds__(256, 2) void proj_gemm(float* __restrict__ out)
{
    extern __shared__ unsigned sm[];
    unsigned* Asb[2] = { sm,            sm + 128*PA };
    unsigned* Bsb[2] = { sm + 2*128*PA, sm + 3*128*PA };
    const unsigned sm_u32 = (unsigned)__cvta_generic_to_shared(sm);
    const unsigned Au[2] = { sm_u32,                sm_u32 + 128*PA*4u };
    const unsigned Bu[2] = { sm_u32 + 2*128*PA*4u,  sm_u32 + 3*128*PA*4u };

    const int tid  = threadIdx.x;
    const int lane = tid & 31;
    const int w    = tid >> 5;
    const int wm   = w >> 2;
    const int wn   = w & 3;
    const int g    = lane >> 2;
    const int t    = lane & 3;
    const int lrow = lane & 15;
    const int lcol = ((lane >> 4) & 1) * 4;
    const int l8   = lane & 7;
    const int lq   = ((lane >> 3) & 1) * 4;
    const int lh   = (lane >> 4) & 1;
    const int bm   = blockIdx.y, bn = blockIdx.x;

    float acc[4][4][4];
    #pragma unroll
    for (int i = 0; i < 4; ++i)
        #pragma unroll
        for (int j = 0; j < 4; ++j)
            #pragma unroll
            for (int q = 0; q < 4; ++q) acc[i][j][q] = 0.f;

    auto load_chunk = [&](int c, int s) {
        #pragma unroll
        for (int u = 0; u < 4; ++u) {
            int id  = tid + 256*u;
            int row = id >> 3, off = (id & 7) * 4;
            int kk = c*32 + off;
            int h = kk >> 6, d = kk & 63;
            int m = bm*128 + row;
            int b = m >> 8, tt = m & 255;
            cp16(Asb[s] + row*PA + off,
                 g_o + (((size_t)(b*NHEAD + h))*SEQ + tt)*HD + d);
            cp16(Bsb[s] + row*PA + off,
                 g_wptT + (size_t)(bn*128 + row)*NEMB + c*32 + off);
        }
        cp_commit();
    };

    load_chunk(0, 0);
    for (int c = 0; c < NCHUNK; ++c) {
        const int s = c & 1;
        if (c + 1 < NCHUNK) { load_chunk(c+1, s^1); cp_wait<1>(); }
        else                { cp_wait<0>(); }
        __syncthreads();

        #pragma unroll
        for (int ks = 0; ks < 4; ++ks) {
            unsigned af[4][4], bf[2][4];
            #pragma unroll
            for (int mf = 0; mf < 4; ++mf)
                ldsm4(af[mf], Au[s] +
                    (((wm*64 + mf*16 + lrow)*PA + ks*8 + lcol) << 2));
            #pragma unroll
            for (int nb = 0; nb < 2; ++nb)
                ldsm4(bf[nb], Bu[s] +
                    (((wn*32 + (nb*2 + lh)*8 + l8)*PA + ks*8 + lq) << 2));
            #pragma unroll
            for (int mf = 0; mf < 4; ++mf)
                #pragma unroll
                for (int nf = 0; nf < 4; ++nf)
                    mma8(acc[mf][nf], af[mf], bf[nf>>1] + (nf&1)*2);
        }
        __syncthreads();
    }

    #pragma unroll
    for (int mf = 0; mf < 4; ++mf) {
        int r0 = bm*128 + wm*64 + mf*16 + g;
        #pragma unroll
        for (int half = 0; half < 2; ++half) {
            int row = r0 + 8*half;
            #pragma unroll
            for (int nf = 0; nf < 4; ++nf) {
                int nn = bn*128 + wn*32 + nf*8 + 2*t;
                *(float2*)(out + (size_t)row*NEMB + nn) =
                    make_float2(acc[mf][nf][2*half], acc[mf][nf][2*half+1]);
            }
        }
    }
}

// ---------------------------------------------------------------------------
extern "C" void kernel_launch(void* const* d_in, const int* in_sizes, int n_in,
                              void* d_out, int out_size)
{
    const float* x      = (const float*)d_in[0];
    const float* w_attn = (const float*)d_in[1];
    const float* w_proj = (const float*)d_in[2];
    float* out = (float*)d_out;

    const int SMEM_GEMM = GEMM_SMEM_WORDS * 4;            // 73728 B
    const int SMEM_ATTN = ATTN_SMEM_WORDS * 4;            // 54272 B
    cudaFuncSetAttribute(qkv_gemm_rope,
        cudaFuncAttributeMaxDynamicSharedMemorySize, SMEM_GEMM);
    cudaFuncSetAttribute(proj_gemm,
        cudaFuncAttributeMaxDynamicSharedMemorySize, SMEM_GEMM);
    cudaFuncSetAttribute(attn_mma,
        cudaFuncAttributeMaxDynamicSharedMemorySize, SMEM_ATTN);

    const int NX4 = MTOT*NEMB/4;
    conv_tf32<<<(NX4 + 255)/256, 256>>>(x, w_attn, w_proj);

    dim3 g1(N_QKV/128, MTOT/128);   // (9, 128)
    qkv_gemm_rope<<<g1, 256, SMEM_GEMM>>>();

    attn_mma<<<2*BH, 256, SMEM_ATTN>>>();   // heavy half first

    dim3 g3(NEMB/128, MTOT/128);    // (3, 128)
    proj_gemm<<<g3, 256, SMEM_GEMM>>>(out);
}